// round 7
// baseline (speedup 1.0000x reference)
#include <cuda_runtime.h>

#define N_VOX 1000000
#define KVOL  27
#define C_IN  3
#define C_HID 64
#define C_OUT 3
#define BN_EPS 1e-5f
#define PBLK  128   // points per block: 8 warps * 4 teams * 4 groups

// Scratch (device globals: allocation-free per harness rules)
__device__ float g_h[(size_t)N_VOX * C_HID];   // 256 MB: conv1 out (pre-BN)
__device__ float g_stats[4 * C_HID];           // sum, sumsq, scale, shift

typedef unsigned long long u64;

__device__ __forceinline__ u64 pack2(float lo, float hi) {
    u64 r; asm("mov.b64 %0, {%1, %2};" : "=l"(r) : "f"(lo), "f"(hi)); return r;
}
__device__ __forceinline__ void unpack2(u64 v, float& lo, float& hi) {
    asm("mov.b64 {%0, %1}, %2;" : "=f"(lo), "=f"(hi) : "l"(v));
}
#define FMA2(d, a, b, c) asm("fma.rn.f32x2 %0, %1, %2, %3;" : "=l"(d) : "l"(a), "l"(b), "l"(c))
#define ADD2(d, a, b)    asm("add.rn.f32x2 %0, %1, %2;"     : "=l"(d) : "l"(a), "l"(b))

__device__ __forceinline__ u64 relu2(u64 v) {
    float a, b; unpack2(v, a, b);
    return pack2(fmaxf(a, 0.f), fmaxf(b, 0.f));
}
// float32x2-correct shuffle-add (shuffle halves as u32 pair, add packed)
__device__ __forceinline__ u64 shfl_add2(u64 v, int delta) {
    u64 o = __shfl_xor_sync(0xffffffffu, v, delta);
    u64 r; ADD2(r, v, o);
    return r;
}

// ---------------------------------------------------------------------------
__global__ void zero_stats_kernel() {
    int i = threadIdx.x;
    if (i < 2 * C_HID) g_stats[i] = 0.f;
}
__global__ void dummy_kernel() {}   // keeps conv1 at ncu capture index 3

// ---------------------------------------------------------------------------
// conv1 (team-sparse, k-union): h[n,:] = sum_{valid k} feats[nbr[k,n]] @ W1[k]
// 8-lane teams (lane owns 8 channels = 4 pairs); 4 teams/warp iterate the
// UNION of their masks so the 768B weight row is read once per union-k
// (mirrored LDS.128 -> 128B unique per instr). Fused BN-stats.
__global__ __launch_bounds__(256) void conv1_kernel(const float* __restrict__ feats,
                                                    const float* __restrict__ W1,
                                                    const int*   __restrict__ nbr) {
    __shared__ u64 w1s[KVOL * 96];                 // [k][c][pair]
    __shared__ int idxs[KVOL * PBLK];
    __shared__ unsigned msk[PBLK];
    __shared__ float sm_s[8][C_HID], sm_s2[8][C_HID];
    const int tid = threadIdx.x;
    {
        const u64* w1g = (const u64*)W1;
        for (int i = tid; i < KVOL * 96; i += 256) w1s[i] = w1g[i];
    }
    const int base = blockIdx.x * PBLK;
    for (int i = tid; i < KVOL * PBLK; i += 256) {
        int k = i / PBLK, pl = i % PBLK;
        int n = base + pl;
        idxs[i] = (n < N_VOX) ? __ldg(&nbr[(size_t)k * N_VOX + n]) : -1;
    }
    __syncthreads();
    if (tid < PBLK) {
        unsigned m = 0;
        #pragma unroll
        for (int k = 0; k < KVOL; k++)
            if (idxs[k * PBLK + tid] >= 0) m |= (1u << k);
        msk[tid] = m;
    }
    __syncthreads();

    const int lane = tid & 31;
    const int wrp  = tid >> 5;
    const int team = lane >> 3;     // 0..3
    const int tl   = lane & 7;      // lane owns pairs 4tl..4tl+3 (ch 8tl..8tl+7)

    u64 ss[4] = {0,0,0,0}, qq[4] = {0,0,0,0};
    const u64 ONE2 = pack2(1.f, 1.f);

    #pragma unroll 1
    for (int g = 0; g < 4; g++) {               // 4 groups of 4 points per warp
        const int pl = wrp * 16 + g * 4 + team;
        const int n  = base + pl;
        const unsigned mt = msk[pl];
        unsigned mu = mt;
        mu |= __shfl_xor_sync(0xffffffffu, mu, 8);
        mu |= __shfl_xor_sync(0xffffffffu, mu, 16);   // union over 4 teams

        u64 acc[4] = {0,0,0,0};
        while (mu) {
            int k = __ffs(mu) - 1;
            mu &= mu - 1;
            if ((mt >> k) & 1u) {
                int id = idxs[k * PBLK + pl];
                float f0 = __ldg(&feats[3 * id + 0]);
                float f1 = __ldg(&feats[3 * id + 1]);
                float f2 = __ldg(&feats[3 * id + 2]);
                const u64* wk = w1s + k * 96 + 4 * tl;
                ulonglong2 wA0 = *(const ulonglong2*)(wk);
                ulonglong2 wA1 = *(const ulonglong2*)(wk + 2);
                ulonglong2 wB0 = *(const ulonglong2*)(wk + 32);
                ulonglong2 wB1 = *(const ulonglong2*)(wk + 34);
                ulonglong2 wC0 = *(const ulonglong2*)(wk + 64);
                ulonglong2 wC1 = *(const ulonglong2*)(wk + 66);
                u64 a0 = pack2(f0, f0), a1 = pack2(f1, f1), a2 = pack2(f2, f2);
                FMA2(acc[0], a0, wA0.x, acc[0]); FMA2(acc[1], a0, wA0.y, acc[1]);
                FMA2(acc[2], a0, wA1.x, acc[2]); FMA2(acc[3], a0, wA1.y, acc[3]);
                FMA2(acc[0], a1, wB0.x, acc[0]); FMA2(acc[1], a1, wB0.y, acc[1]);
                FMA2(acc[2], a1, wB1.x, acc[2]); FMA2(acc[3], a1, wB1.y, acc[3]);
                FMA2(acc[0], a2, wC0.x, acc[0]); FMA2(acc[1], a2, wC0.y, acc[1]);
                FMA2(acc[2], a2, wC1.x, acc[2]); FMA2(acc[3], a2, wC1.y, acc[3]);
            }
        }
        if (n < N_VOX) {
            ulonglong2* ho = (ulonglong2*)(g_h + (size_t)n * C_HID) + 2 * tl;
            ho[0] = make_ulonglong2(acc[0], acc[1]);
            ho[1] = make_ulonglong2(acc[2], acc[3]);
            #pragma unroll
            for (int j = 0; j < 4; j++) {
                FMA2(ss[j], acc[j], ONE2,   ss[j]);
                FMA2(qq[j], acc[j], acc[j], qq[j]);
            }
        }
    }

    // stats reduce: lanes tl, tl+8, tl+16, tl+24 share the same channel set.
    // Packed float add via shuffled u64 halves (ADD2 = add.rn.f32x2).
    #pragma unroll
    for (int j = 0; j < 4; j++) {
        ss[j] = shfl_add2(ss[j], 8);  ss[j] = shfl_add2(ss[j], 16);
        qq[j] = shfl_add2(qq[j], 8);  qq[j] = shfl_add2(qq[j], 16);
    }
    if (lane < 8) {
        #pragma unroll
        for (int j = 0; j < 4; j++) {
            float a, b, c, d;
            unpack2(ss[j], a, b);
            unpack2(qq[j], c, d);
            sm_s [wrp][8 * tl + 2 * j + 0] = a;
            sm_s [wrp][8 * tl + 2 * j + 1] = b;
            sm_s2[wrp][8 * tl + 2 * j + 0] = c;
            sm_s2[wrp][8 * tl + 2 * j + 1] = d;
        }
    }
    __syncthreads();
    if (tid < C_HID) {
        float t = 0.f, t2 = 0.f;
        #pragma unroll
        for (int w = 0; w < 8; w++) { t += sm_s[w][tid]; t2 += sm_s2[w][tid]; }
        atomicAdd(&g_stats[tid], t);
        atomicAdd(&g_stats[C_HID + tid], t2);
    }
}

// ---------------------------------------------------------------------------
__global__ void finalize_kernel(const float* __restrict__ gamma,
                                const float* __restrict__ beta) {
    int d = threadIdx.x;
    if (d < C_HID) {
        float mu  = g_stats[d] * (1.f / N_VOX);
        float var = g_stats[C_HID + d] * (1.f / N_VOX) - mu * mu;
        float sc  = gamma[d] * rsqrtf(var + BN_EPS);
        g_stats[2 * C_HID + d] = sc;
        g_stats[3 * C_HID + d] = beta[d] - mu * sc;
    }
}

// ---------------------------------------------------------------------------
// conv2 (team-sparse, k-union): out[n] = sum_k relu(bn(h[nbr[k,n]])) @ W2[26-k]
__global__ __launch_bounds__(256) void conv2_kernel(const float* __restrict__ W2,
                                                    const int*   __restrict__ nbr,
                                                    float* __restrict__ out) {
    __shared__ u64 w2t[KVOL * 96];                 // [k][c][pair], k -> W2[26-k]
    __shared__ int idxs[KVOL * PBLK];
    __shared__ unsigned msk[PBLK];
    const int tid = threadIdx.x;
    {
        float* w2tf = (float*)w2t;
        for (int i = tid; i < KVOL * C_OUT * C_HID; i += 256) {
            int kk  = i / (C_OUT * C_HID);
            int rem = i % (C_OUT * C_HID);
            int c   = rem / C_HID;
            int d   = rem % C_HID;
            w2tf[(kk * C_OUT + c) * C_HID + d] =
                W2[(size_t)(KVOL - 1 - kk) * (C_HID * C_OUT) + d * C_OUT + c];
        }
    }
    const int base = blockIdx.x * PBLK;
    for (int i = tid; i < KVOL * PBLK; i += 256) {
        int k = i / PBLK, pl = i % PBLK;
        int n = base + pl;
        idxs[i] = (n < N_VOX) ? __ldg(&nbr[(size_t)k * N_VOX + n]) : -1;
    }
    __syncthreads();
    if (tid < PBLK) {
        unsigned m = 0;
        #pragma unroll
        for (int k = 0; k < KVOL; k++)
            if (idxs[k * PBLK + tid] >= 0) m |= (1u << k);
        msk[tid] = m;
    }
    __syncthreads();

    const int lane = tid & 31;
    const int wrp  = tid >> 5;
    const int team = lane >> 3;
    const int tl   = lane & 7;

    u64 sc[4], sh[4];
    #pragma unroll
    for (int j = 0; j < 4; j++) {
        sc[j] = pack2(g_stats[2 * C_HID + 8 * tl + 2 * j],
                      g_stats[2 * C_HID + 8 * tl + 2 * j + 1]);
        sh[j] = pack2(g_stats[3 * C_HID + 8 * tl + 2 * j],
                      g_stats[3 * C_HID + 8 * tl + 2 * j + 1]);
    }

    #pragma unroll 1
    for (int g = 0; g < 4; g++) {
        const int pl = wrp * 16 + g * 4 + team;
        const int n  = base + pl;
        const unsigned mt = msk[pl];
        unsigned mu = mt;
        mu |= __shfl_xor_sync(0xffffffffu, mu, 8);
        mu |= __shfl_xor_sync(0xffffffffu, mu, 16);

        u64 acc0 = 0ull, acc1 = 0ull, acc2 = 0ull;
        while (mu) {
            int k = __ffs(mu) - 1;
            mu &= mu - 1;
            if ((mt >> k) & 1u) {
                int id = idxs[k * PBLK + pl];
                const ulonglong2* hp =
                    (const ulonglong2*)(g_h + (size_t)id * C_HID) + 2 * tl;
                ulonglong2 h0 = __ldg(hp), h1 = __ldg(hp + 1);
                u64 hv0 = h0.x, hv1 = h0.y, hv2 = h1.x, hv3 = h1.y;
                FMA2(hv0, hv0, sc[0], sh[0]); hv0 = relu2(hv0);
                FMA2(hv1, hv1, sc[1], sh[1]); hv1 = relu2(hv1);
                FMA2(hv2, hv2, sc[2], sh[2]); hv2 = relu2(hv2);
                FMA2(hv3, hv3, sc[3], sh[3]); hv3 = relu2(hv3);
                const u64* wk = w2t + k * 96 + 4 * tl;
                ulonglong2 wA0 = *(const ulonglong2*)(wk);
                ulonglong2 wA1 = *(const ulonglong2*)(wk + 2);
                ulonglong2 wB0 = *(const ulonglong2*)(wk + 32);
                ulonglong2 wB1 = *(const ulonglong2*)(wk + 34);
                ulonglong2 wC0 = *(const ulonglong2*)(wk + 64);
                ulonglong2 wC1 = *(const ulonglong2*)(wk + 66);
                FMA2(acc0, hv0, wA0.x, acc0); FMA2(acc0, hv1, wA0.y, acc0);
                FMA2(acc0, hv2, wA1.x, acc0); FMA2(acc0, hv3, wA1.y, acc0);
                FMA2(acc1, hv0, wB0.x, acc1); FMA2(acc1, hv1, wB0.y, acc1);
                FMA2(acc1, hv2, wB1.x, acc1); FMA2(acc1, hv3, wB1.y, acc1);
                FMA2(acc2, hv0, wC0.x, acc2); FMA2(acc2, hv1, wC0.y, acc2);
                FMA2(acc2, hv2, wC1.x, acc2); FMA2(acc2, hv3, wC1.y, acc2);
            }
        }
        float r0, r1, r2;
        { float lo, hi; unpack2(acc0, lo, hi); r0 = lo + hi; }
        { float lo, hi; unpack2(acc1, lo, hi); r1 = lo + hi; }
        { float lo, hi; unpack2(acc2, lo, hi); r2 = lo + hi; }
        #pragma unroll
        for (int o = 4; o >= 1; o >>= 1) {      // reduce within 8-lane team
            r0 += __shfl_xor_sync(0xffffffffu, r0, o);
            r1 += __shfl_xor_sync(0xffffffffu, r1, o);
            r2 += __shfl_xor_sync(0xffffffffu, r2, o);
        }
        if (tl == 0 && n < N_VOX) {
            out[3 * n + 0] = r0;
            out[3 * n + 1] = r1;
            out[3 * n + 2] = r2;
        }
    }
}

// ---------------------------------------------------------------------------
extern "C" void kernel_launch(void* const* d_in, const int* in_sizes, int n_in,
                              void* d_out, int out_size) {
    const float* feats = (const float*)d_in[0];
    const float* W1    = (const float*)d_in[1];
    const float* gamma = (const float*)d_in[2];
    const float* beta  = (const float*)d_in[3];
    const float* W2    = (const float*)d_in[4];
    const int*   nbr   = (const int*)  d_in[5];
    float*       out   = (float*)d_out;

    const int nblk = (N_VOX + PBLK - 1) / PBLK;

    zero_stats_kernel<<<1, 128>>>();                    // 0
    dummy_kernel<<<1, 32>>>();                          // 1
    dummy_kernel<<<1, 32>>>();                          // 2
    conv1_kernel<<<nblk, 256>>>(feats, W1, nbr);        // 3 <- ncu
    finalize_kernel<<<1, 64>>>(gamma, beta);            // 4
    conv2_kernel<<<nblk, 256>>>(W2, nbr, out);          // 5
}

// round 8
// speedup vs baseline: 1.0116x; 1.0116x over previous
#include <cuda_runtime.h>

#define N_VOX 1000000
#define KVOL  27
#define C_IN  3
#define C_HID 64
#define C_OUT 3
#define BN_EPS 1e-5f
#define PBLK  128   // points per block: 8 warps * 4 teams * 4 groups

// Scratch (device globals: allocation-free per harness rules)
__device__ float g_h[(size_t)N_VOX * C_HID];   // 256 MB: conv1 out (pre-BN)
__device__ float g_stats[4 * C_HID];           // sum, sumsq, scale, shift

typedef unsigned long long u64;

__device__ __forceinline__ u64 pack2(float lo, float hi) {
    u64 r; asm("mov.b64 %0, {%1, %2};" : "=l"(r) : "f"(lo), "f"(hi)); return r;
}
__device__ __forceinline__ void unpack2(u64 v, float& lo, float& hi) {
    asm("mov.b64 {%0, %1}, %2;" : "=f"(lo), "=f"(hi) : "l"(v));
}
#define FMA2(d, a, b, c) asm("fma.rn.f32x2 %0, %1, %2, %3;" : "=l"(d) : "l"(a), "l"(b), "l"(c))
#define ADD2(d, a, b)    asm("add.rn.f32x2 %0, %1, %2;"     : "=l"(d) : "l"(a), "l"(b))

__device__ __forceinline__ u64 relu2(u64 v) {
    float a, b; unpack2(v, a, b);
    return pack2(fmaxf(a, 0.f), fmaxf(b, 0.f));
}
__device__ __forceinline__ u64 shfl_add2(u64 v, int delta) {
    u64 o = __shfl_xor_sync(0xffffffffu, v, delta);
    u64 r; ADD2(r, v, o);
    return r;
}

// ---------------------------------------------------------------------------
__global__ void zero_stats_kernel() {
    int i = threadIdx.x;
    if (i < 2 * C_HID) g_stats[i] = 0.f;
}
__global__ void dummy_kernel() {}   // keeps conv1 at ncu capture index 3

// ---------------------------------------------------------------------------
// conv1 (team-sparse, k-union, conflict-free weight planes).
// 8-lane teams; lane tl owns channels 8tl..8tl+7 (pairs 4tl..4tl+3).
// Weight planes: A[(k*3+c)*8 + tl] = pairs (4tl,4tl+1), B = (4tl+2,4tl+3).
// Each (k,c) plane row = 8 contiguous 16B chunks = 1 conflict-free wavefront
// shared by all 4 teams (same-address broadcast dedup). Fused BN-stats.
__global__ __launch_bounds__(256) void conv1_kernel(const float* __restrict__ feats,
                                                    const float* __restrict__ W1,
                                                    const int*   __restrict__ nbr) {
    __shared__ ulonglong2 wA[KVOL * 24];   // 10.4 KB
    __shared__ ulonglong2 wB[KVOL * 24];   // 10.4 KB
    __shared__ int idxs[KVOL * PBLK];      // 13.8 KB
    __shared__ unsigned msk[PBLK];
    __shared__ float sm_s[8][C_HID], sm_s2[8][C_HID];
    const int tid = threadIdx.x;
    {
        const u64* w1g = (const u64*)W1;   // pair index = (k*3+c)*32 + p
        for (int i = tid; i < KVOL * 24; i += 256) {
            int kc = i >> 3, tl = i & 7;
            int b = kc * 32 + 4 * tl;
            wA[i] = make_ulonglong2(w1g[b],     w1g[b + 1]);
            wB[i] = make_ulonglong2(w1g[b + 2], w1g[b + 3]);
        }
    }
    const int base = blockIdx.x * PBLK;
    for (int i = tid; i < KVOL * PBLK; i += 256) {
        int k = i / PBLK, pl = i % PBLK;
        int n = base + pl;
        idxs[i] = (n < N_VOX) ? __ldg(&nbr[(size_t)k * N_VOX + n]) : -1;
    }
    __syncthreads();
    if (tid < PBLK) {
        unsigned m = 0;
        #pragma unroll
        for (int k = 0; k < KVOL; k++)
            if (idxs[k * PBLK + tid] >= 0) m |= (1u << k);
        msk[tid] = m;
    }
    __syncthreads();

    const int lane = tid & 31;
    const int wrp  = tid >> 5;
    const int team = lane >> 3;     // 0..3
    const int tl   = lane & 7;

    u64 ss[4] = {0,0,0,0}, qq[4] = {0,0,0,0};
    const u64 ONE2 = pack2(1.f, 1.f);

    #pragma unroll 1
    for (int g = 0; g < 4; g++) {               // 4 consecutive points per warp
        const int pl = wrp * 16 + g * 4 + team;
        const int n  = base + pl;
        const unsigned mt = msk[pl];
        unsigned mu = mt;
        mu |= __shfl_xor_sync(0xffffffffu, mu, 8);
        mu |= __shfl_xor_sync(0xffffffffu, mu, 16);   // union over 4 teams

        u64 acc0 = 0ull, acc1 = 0ull, acc2 = 0ull, acc3 = 0ull;
        while (mu) {
            int k = __ffs(mu) - 1;
            mu &= mu - 1;
            if ((mt >> k) & 1u) {
                int id = idxs[k * PBLK + pl];
                float f0 = __ldg(&feats[3 * id + 0]);
                float f1 = __ldg(&feats[3 * id + 1]);
                float f2 = __ldg(&feats[3 * id + 2]);
                const int wb = k * 24 + tl;
                ulonglong2 A0 = wA[wb], A1 = wA[wb + 8], A2 = wA[wb + 16];
                ulonglong2 B0 = wB[wb], B1 = wB[wb + 8], B2 = wB[wb + 16];
                u64 a0 = pack2(f0, f0), a1 = pack2(f1, f1), a2 = pack2(f2, f2);
                FMA2(acc0, a0, A0.x, acc0); FMA2(acc1, a0, A0.y, acc1);
                FMA2(acc2, a0, B0.x, acc2); FMA2(acc3, a0, B0.y, acc3);
                FMA2(acc0, a1, A1.x, acc0); FMA2(acc1, a1, A1.y, acc1);
                FMA2(acc2, a1, B1.x, acc2); FMA2(acc3, a1, B1.y, acc3);
                FMA2(acc0, a2, A2.x, acc0); FMA2(acc1, a2, A2.y, acc1);
                FMA2(acc2, a2, B2.x, acc2); FMA2(acc3, a2, B2.y, acc3);
            }
        }
        if (n < N_VOX) {
            ulonglong2* ho = (ulonglong2*)(g_h + (size_t)n * C_HID + 8 * tl);
            ho[0] = make_ulonglong2(acc0, acc1);
            ho[1] = make_ulonglong2(acc2, acc3);
            FMA2(ss[0], acc0, ONE2, ss[0]); FMA2(qq[0], acc0, acc0, qq[0]);
            FMA2(ss[1], acc1, ONE2, ss[1]); FMA2(qq[1], acc1, acc1, qq[1]);
            FMA2(ss[2], acc2, ONE2, ss[2]); FMA2(qq[2], acc2, acc2, qq[2]);
            FMA2(ss[3], acc3, ONE2, ss[3]); FMA2(qq[3], acc3, acc3, qq[3]);
        }
    }

    // stats reduce across the 4 teams (lanes tl, tl+8, tl+16, tl+24 share chans)
    #pragma unroll
    for (int j = 0; j < 4; j++) {
        ss[j] = shfl_add2(ss[j], 8);  ss[j] = shfl_add2(ss[j], 16);
        qq[j] = shfl_add2(qq[j], 8);  qq[j] = shfl_add2(qq[j], 16);
    }
    if (lane < 8) {
        #pragma unroll
        for (int j = 0; j < 4; j++) {
            float a, b, c, d;
            unpack2(ss[j], a, b);
            unpack2(qq[j], c, d);
            sm_s [wrp][8 * tl + 2 * j + 0] = a;
            sm_s [wrp][8 * tl + 2 * j + 1] = b;
            sm_s2[wrp][8 * tl + 2 * j + 0] = c;
            sm_s2[wrp][8 * tl + 2 * j + 1] = d;
        }
    }
    __syncthreads();
    if (tid < C_HID) {
        float t = 0.f, t2 = 0.f;
        #pragma unroll
        for (int w = 0; w < 8; w++) { t += sm_s[w][tid]; t2 += sm_s2[w][tid]; }
        atomicAdd(&g_stats[tid], t);
        atomicAdd(&g_stats[C_HID + tid], t2);
    }
}

// ---------------------------------------------------------------------------
__global__ void finalize_kernel(const float* __restrict__ gamma,
                                const float* __restrict__ beta) {
    int d = threadIdx.x;
    if (d < C_HID) {
        float mu  = g_stats[d] * (1.f / N_VOX);
        float var = g_stats[C_HID + d] * (1.f / N_VOX) - mu * mu;
        float sc  = gamma[d] * rsqrtf(var + BN_EPS);
        g_stats[2 * C_HID + d] = sc;
        g_stats[3 * C_HID + d] = beta[d] - mu * sc;
    }
}

// ---------------------------------------------------------------------------
// conv2 (team-sparse, k-union, conflict-free weight planes):
// out[n] = sum_k relu(bn(h[nbr[k,n]])) @ W2[26-k].  BN+ReLU in registers.
__global__ __launch_bounds__(256) void conv2_kernel(const float* __restrict__ W2,
                                                    const int*   __restrict__ nbr,
                                                    float* __restrict__ out) {
    __shared__ ulonglong2 wA[KVOL * 24];   // A: pairs (4tl,4tl+1) of wt[k][c][:]
    __shared__ ulonglong2 wB[KVOL * 24];   // B: pairs (4tl+2,4tl+3)
    __shared__ int idxs[KVOL * PBLK];
    __shared__ unsigned msk[PBLK];
    const int tid = threadIdx.x;
    {
        // wt[k][c][d] = W2[26-k][d][c]; fill planes float-wise
        float* fA = (float*)wA;
        float* fB = (float*)wB;
        for (int i = tid; i < KVOL * C_OUT * C_HID; i += 256) {
            int k   = i / (C_OUT * C_HID);
            int rem = i % (C_OUT * C_HID);
            int c   = rem / C_HID;
            int d   = rem % C_HID;
            float v = W2[(size_t)(KVOL - 1 - k) * (C_HID * C_OUT) + d * C_OUT + c];
            int tl = d >> 3, j = d & 7;
            int slot = ((k * 3 + c) * 8 + tl) * 4;
            if (j < 4) fA[slot + j] = v;
            else       fB[slot + (j - 4)] = v;
        }
    }
    const int base = blockIdx.x * PBLK;
    for (int i = tid; i < KVOL * PBLK; i += 256) {
        int k = i / PBLK, pl = i % PBLK;
        int n = base + pl;
        idxs[i] = (n < N_VOX) ? __ldg(&nbr[(size_t)k * N_VOX + n]) : -1;
    }
    __syncthreads();
    if (tid < PBLK) {
        unsigned m = 0;
        #pragma unroll
        for (int k = 0; k < KVOL; k++)
            if (idxs[k * PBLK + tid] >= 0) m |= (1u << k);
        msk[tid] = m;
    }
    __syncthreads();

    const int lane = tid & 31;
    const int wrp  = tid >> 5;
    const int team = lane >> 3;
    const int tl   = lane & 7;

    u64 sc[4], sh[4];
    #pragma unroll
    for (int j = 0; j < 4; j++) {
        sc[j] = pack2(g_stats[2 * C_HID + 8 * tl + 2 * j],
                      g_stats[2 * C_HID + 8 * tl + 2 * j + 1]);
        sh[j] = pack2(g_stats[3 * C_HID + 8 * tl + 2 * j],
                      g_stats[3 * C_HID + 8 * tl + 2 * j + 1]);
    }

    #pragma unroll 1
    for (int g = 0; g < 4; g++) {
        const int pl = wrp * 16 + g * 4 + team;
        const int n  = base + pl;
        const unsigned mt = msk[pl];
        unsigned mu = mt;
        mu |= __shfl_xor_sync(0xffffffffu, mu, 8);
        mu |= __shfl_xor_sync(0xffffffffu, mu, 16);

        u64 acc0 = 0ull, acc1 = 0ull, acc2 = 0ull;
        while (mu) {
            int k = __ffs(mu) - 1;
            mu &= mu - 1;
            if ((mt >> k) & 1u) {
                int id = idxs[k * PBLK + pl];
                const ulonglong2* hp =
                    (const ulonglong2*)(g_h + (size_t)id * C_HID + 8 * tl);
                ulonglong2 h0 = __ldg(hp), h1 = __ldg(hp + 1);
                u64 hv0 = h0.x, hv1 = h0.y, hv2 = h1.x, hv3 = h1.y;
                FMA2(hv0, hv0, sc[0], sh[0]); hv0 = relu2(hv0);
                FMA2(hv1, hv1, sc[1], sh[1]); hv1 = relu2(hv1);
                FMA2(hv2, hv2, sc[2], sh[2]); hv2 = relu2(hv2);
                FMA2(hv3, hv3, sc[3], sh[3]); hv3 = relu2(hv3);
                const int wb = k * 24 + tl;
                ulonglong2 A0 = wA[wb], A1 = wA[wb + 8], A2 = wA[wb + 16];
                ulonglong2 B0 = wB[wb], B1 = wB[wb + 8], B2 = wB[wb + 16];
                FMA2(acc0, hv0, A0.x, acc0); FMA2(acc0, hv1, A0.y, acc0);
                FMA2(acc0, hv2, B0.x, acc0); FMA2(acc0, hv3, B0.y, acc0);
                FMA2(acc1, hv0, A1.x, acc1); FMA2(acc1, hv1, A1.y, acc1);
                FMA2(acc1, hv2, B1.x, acc1); FMA2(acc1, hv3, B1.y, acc1);
                FMA2(acc2, hv0, A2.x, acc2); FMA2(acc2, hv1, A2.y, acc2);
                FMA2(acc2, hv2, B2.x, acc2); FMA2(acc2, hv3, B2.y, acc2);
            }
        }
        float r0, r1, r2;
        { float lo, hi; unpack2(acc0, lo, hi); r0 = lo + hi; }
        { float lo, hi; unpack2(acc1, lo, hi); r1 = lo + hi; }
        { float lo, hi; unpack2(acc2, lo, hi); r2 = lo + hi; }
        #pragma unroll
        for (int o = 4; o >= 1; o >>= 1) {      // reduce within 8-lane team
            r0 += __shfl_xor_sync(0xffffffffu, r0, o);
            r1 += __shfl_xor_sync(0xffffffffu, r1, o);
            r2 += __shfl_xor_sync(0xffffffffu, r2, o);
        }
        if (tl == 0 && n < N_VOX) {
            out[3 * n + 0] = r0;
            out[3 * n + 1] = r1;
            out[3 * n + 2] = r2;
        }
    }
}

// ---------------------------------------------------------------------------
extern "C" void kernel_launch(void* const* d_in, const int* in_sizes, int n_in,
                              void* d_out, int out_size) {
    const float* feats = (const float*)d_in[0];
    const float* W1    = (const float*)d_in[1];
    const float* gamma = (const float*)d_in[2];
    const float* beta  = (const float*)d_in[3];
    const float* W2    = (const float*)d_in[4];
    const int*   nbr   = (const int*)  d_in[5];
    float*       out   = (float*)d_out;

    const int nblk = (N_VOX + PBLK - 1) / PBLK;

    zero_stats_kernel<<<1, 128>>>();                    // 0
    dummy_kernel<<<1, 32>>>();                          // 1
    dummy_kernel<<<1, 32>>>();                          // 2
    conv1_kernel<<<nblk, 256>>>(feats, W1, nbr);        // 3 <- ncu
    finalize_kernel<<<1, 64>>>(gamma, beta);            // 4
    conv2_kernel<<<nblk, 256>>>(W2, nbr, out);          // 5
}

// round 9
// speedup vs baseline: 1.6384x; 1.6197x over previous
#include <cuda_runtime.h>

#define N_VOX 1000000
#define KVOL  27
#define C_IN  3
#define C_HID 64
#define C_OUT 3
#define BN_EPS 1e-5f
#define PBLK  128   // points per block (256 thr = 16 teams of 16 lanes, 8 pts/team-pair)

// Scratch (device globals: allocation-free per harness rules)
__device__ float g_h[(size_t)N_VOX * C_HID];   // 256 MB: conv1 out (pre-BN)
__device__ float g_stats[4 * C_HID];           // sum, sumsq, scale, shift

typedef unsigned long long u64;

__device__ __forceinline__ u64 pack2(float lo, float hi) {
    u64 r; asm("mov.b64 %0, {%1, %2};" : "=l"(r) : "f"(lo), "f"(hi)); return r;
}
__device__ __forceinline__ void unpack2(u64 v, float& lo, float& hi) {
    asm("mov.b64 {%0, %1}, %2;" : "=f"(lo), "=f"(hi) : "l"(v));
}
#define FMA2(d, a, b, c) asm("fma.rn.f32x2 %0, %1, %2, %3;" : "=l"(d) : "l"(a), "l"(b), "l"(c))

__device__ __forceinline__ u64 relu2(u64 v) {
    float a, b; unpack2(v, a, b);
    return pack2(fmaxf(a, 0.f), fmaxf(b, 0.f));
}

// ---------------------------------------------------------------------------
__global__ void zero_stats_kernel() {
    int i = threadIdx.x;
    if (i < 2 * C_HID) g_stats[i] = 0.f;
}
__global__ void dummy_kernel() {}   // keeps conv1 at ncu capture index 3

// ---------------------------------------------------------------------------
// conv1 (team-sparse, R6 structure + conflict-free weight planes):
// h[n,:] = sum_{valid k} feats[nbr[k,n]] @ W1[k]
// 16-lane teams own one point; lane tl owns channels 4tl..4tl+3 (pairs 2tl,2tl+1).
// Weight plane w1p[(k*3+c)*16 + tl] = ulonglong2(pair 2tl, pair 2tl+1):
// each (k,c) row is 256B contiguous -> 2 wavefronts per 16-lane half, no conflicts.
// Masked while-loop visits only valid k (~4.7 avg per point). Fused BN-stats.
__global__ __launch_bounds__(256) void conv1_kernel(const float* __restrict__ feats,
                                                    const float* __restrict__ W1,
                                                    const int*   __restrict__ nbr) {
    __shared__ ulonglong2 w1p[KVOL * 3 * 16];      // 20.7 KB
    __shared__ int idxs[KVOL * PBLK];              // 13.8 KB
    __shared__ unsigned msk[PBLK];
    __shared__ float sm_s[8][C_HID], sm_s2[8][C_HID];
    const int tid = threadIdx.x;
    {
        const u64* w1g = (const u64*)W1;           // pair index = (k*3+c)*32 + p
        for (int i = tid; i < KVOL * 3 * 16; i += 256) {
            int kc = i >> 4, t = i & 15;
            int b = kc * 32 + 2 * t;
            w1p[i] = make_ulonglong2(w1g[b], w1g[b + 1]);
        }
    }
    const int base = blockIdx.x * PBLK;
    for (int i = tid; i < KVOL * PBLK; i += 256) {
        int k = i / PBLK, pl = i % PBLK;
        int n = base + pl;
        idxs[i] = (n < N_VOX) ? __ldg(&nbr[(size_t)k * N_VOX + n]) : -1;
    }
    __syncthreads();
    if (tid < PBLK) {
        unsigned m = 0;
        #pragma unroll
        for (int k = 0; k < KVOL; k++)
            if (idxs[k * PBLK + tid] >= 0) m |= (1u << k);
        msk[tid] = m;
    }
    __syncthreads();

    const int lane  = tid & 31;
    const int wrp   = tid >> 5;
    const int tlane = lane & 15;
    const int half  = lane >> 4;

    float s0 = 0.f, s1 = 0.f, s2v = 0.f, s3 = 0.f;
    float q0 = 0.f, q1 = 0.f, q2 = 0.f, q3 = 0.f;

    #pragma unroll 1
    for (int pp = 0; pp < PBLK / 16; pp++) {        // 8 point-pairs per warp
        const int pl = (wrp * (PBLK / 16) + pp) * 2 + half;
        const int n  = base + pl;

        u64 acc0 = 0ull, acc1 = 0ull;               // channels 4t..4t+3
        unsigned m = msk[pl];
        while (m) {
            int k = __ffs(m) - 1;
            m &= m - 1;
            int id = idxs[k * PBLK + pl];
            float f0 = __ldg(&feats[3 * id + 0]);
            float f1 = __ldg(&feats[3 * id + 1]);
            float f2 = __ldg(&feats[3 * id + 2]);
            const ulonglong2* wp = w1p + k * 48 + tlane;
            ulonglong2 w0 = wp[0], w1v = wp[16], w2v = wp[32];
            u64 a0 = pack2(f0, f0), a1 = pack2(f1, f1), a2 = pack2(f2, f2);
            FMA2(acc0, a0, w0.x,  acc0); FMA2(acc1, a0, w0.y,  acc1);
            FMA2(acc0, a1, w1v.x, acc0); FMA2(acc1, a1, w1v.y, acc1);
            FMA2(acc0, a2, w2v.x, acc0); FMA2(acc1, a2, w2v.y, acc1);
        }
        if (n < N_VOX) {
            ulonglong2* ho = (ulonglong2*)(g_h + (size_t)n * C_HID) + tlane;
            *ho = make_ulonglong2(acc0, acc1);
            float h0, h1, h2, h3;
            unpack2(acc0, h0, h1);
            unpack2(acc1, h2, h3);
            s0 += h0; s1 += h1; s2v += h2; s3 += h3;
            q0 = fmaf(h0, h0, q0); q1 = fmaf(h1, h1, q1);
            q2 = fmaf(h2, h2, q2); q3 = fmaf(h3, h3, q3);
        }
    }

    // stats reduction: lane^16 shares the same channel set
    s0 += __shfl_xor_sync(0xffffffffu, s0, 16);
    s1 += __shfl_xor_sync(0xffffffffu, s1, 16);
    s2v += __shfl_xor_sync(0xffffffffu, s2v, 16);
    s3 += __shfl_xor_sync(0xffffffffu, s3, 16);
    q0 += __shfl_xor_sync(0xffffffffu, q0, 16);
    q1 += __shfl_xor_sync(0xffffffffu, q1, 16);
    q2 += __shfl_xor_sync(0xffffffffu, q2, 16);
    q3 += __shfl_xor_sync(0xffffffffu, q3, 16);
    if (lane < 16) {
        sm_s [wrp][4 * tlane + 0] = s0;  sm_s [wrp][4 * tlane + 1] = s1;
        sm_s [wrp][4 * tlane + 2] = s2v; sm_s [wrp][4 * tlane + 3] = s3;
        sm_s2[wrp][4 * tlane + 0] = q0;  sm_s2[wrp][4 * tlane + 1] = q1;
        sm_s2[wrp][4 * tlane + 2] = q2;  sm_s2[wrp][4 * tlane + 3] = q3;
    }
    __syncthreads();
    if (tid < C_HID) {
        float t = 0.f, t2 = 0.f;
        #pragma unroll
        for (int w = 0; w < 8; w++) { t += sm_s[w][tid]; t2 += sm_s2[w][tid]; }
        atomicAdd(&g_stats[tid], t);
        atomicAdd(&g_stats[C_HID + tid], t2);
    }
}

// ---------------------------------------------------------------------------
__global__ void finalize_kernel(const float* __restrict__ gamma,
                                const float* __restrict__ beta) {
    int d = threadIdx.x;
    if (d < C_HID) {
        float mu  = g_stats[d] * (1.f / N_VOX);
        float var = g_stats[C_HID + d] * (1.f / N_VOX) - mu * mu;
        float sc  = gamma[d] * rsqrtf(var + BN_EPS);
        g_stats[2 * C_HID + d] = sc;
        g_stats[3 * C_HID + d] = beta[d] - mu * sc;
    }
}

// ---------------------------------------------------------------------------
// conv2 (team-sparse, R6 structure + conflict-free weight planes):
// out[n] = sum_k valid * ( relu(bn(h[nbr[k,n]])) @ W2[26-k] )
// 16-lane teams, masked k loop, BN+ReLU in registers at gather time.
__global__ __launch_bounds__(256) void conv2_kernel(const float* __restrict__ W2,
                                                    const int*   __restrict__ nbr,
                                                    float* __restrict__ out) {
    __shared__ ulonglong2 w2p[KVOL * 3 * 16];      // plane: [(k*3+c)*16 + tl]
    __shared__ int idxs[KVOL * PBLK];
    __shared__ unsigned msk[PBLK];
    const int tid = threadIdx.x;
    {
        // wt[k][c][d] = W2[26-k][d][c]; lane tl gets channels 4tl..4tl+3
        float* fp = (float*)w2p;
        for (int i = tid; i < KVOL * C_OUT * C_HID; i += 256) {
            int k   = i / (C_OUT * C_HID);
            int rem = i % (C_OUT * C_HID);
            int c   = rem / C_HID;
            int d   = rem % C_HID;
            float v = W2[(size_t)(KVOL - 1 - k) * (C_HID * C_OUT) + d * C_OUT + c];
            int t = d >> 2, j = d & 3;
            fp[((k * 3 + c) * 16 + t) * 4 + j] = v;
        }
    }
    const int base = blockIdx.x * PBLK;
    for (int i = tid; i < KVOL * PBLK; i += 256) {
        int k = i / PBLK, pl = i % PBLK;
        int n = base + pl;
        idxs[i] = (n < N_VOX) ? __ldg(&nbr[(size_t)k * N_VOX + n]) : -1;
    }
    __syncthreads();
    if (tid < PBLK) {
        unsigned m = 0;
        #pragma unroll
        for (int k = 0; k < KVOL; k++)
            if (idxs[k * PBLK + tid] >= 0) m |= (1u << k);
        msk[tid] = m;
    }
    __syncthreads();

    const int lane  = tid & 31;
    const int wrp   = tid >> 5;
    const int tlane = lane & 15;
    const int half  = lane >> 4;

    // BN scale/shift for this lane's 4 channels (packed for FMA2)
    const u64 scA = pack2(g_stats[2 * C_HID + 4 * tlane + 0], g_stats[2 * C_HID + 4 * tlane + 1]);
    const u64 scB = pack2(g_stats[2 * C_HID + 4 * tlane + 2], g_stats[2 * C_HID + 4 * tlane + 3]);
    const u64 shA = pack2(g_stats[3 * C_HID + 4 * tlane + 0], g_stats[3 * C_HID + 4 * tlane + 1]);
    const u64 shB = pack2(g_stats[3 * C_HID + 4 * tlane + 2], g_stats[3 * C_HID + 4 * tlane + 3]);

    #pragma unroll 1
    for (int pp = 0; pp < PBLK / 16; pp++) {        // 8 point-pairs per warp
        const int pl = (wrp * (PBLK / 16) + pp) * 2 + half;
        const int n  = base + pl;

        u64 acc0 = 0ull, acc1 = 0ull, acc2 = 0ull;
        unsigned m = msk[pl];
        while (m) {
            int k = __ffs(m) - 1;
            m &= m - 1;
            int id = idxs[k * PBLK + pl];
            ulonglong2 hv = __ldg((const ulonglong2*)(g_h + (size_t)id * C_HID) + tlane);
            FMA2(hv.x, hv.x, scA, shA);
            FMA2(hv.y, hv.y, scB, shB);
            hv.x = relu2(hv.x);
            hv.y = relu2(hv.y);
            const ulonglong2* wp = w2p + k * 48 + tlane;
            ulonglong2 w0 = wp[0], w1 = wp[16], w2v = wp[32];
            FMA2(acc0, hv.x, w0.x,  acc0); FMA2(acc0, hv.y, w0.y,  acc0);
            FMA2(acc1, hv.x, w1.x,  acc1); FMA2(acc1, hv.y, w1.y,  acc1);
            FMA2(acc2, hv.x, w2v.x, acc2); FMA2(acc2, hv.y, w2v.y, acc2);
        }
        float r0, r1, r2;
        { float lo, hi; unpack2(acc0, lo, hi); r0 = lo + hi; }
        { float lo, hi; unpack2(acc1, lo, hi); r1 = lo + hi; }
        { float lo, hi; unpack2(acc2, lo, hi); r2 = lo + hi; }
        #pragma unroll
        for (int o = 8; o >= 1; o >>= 1) {
            r0 += __shfl_xor_sync(0xffffffffu, r0, o);
            r1 += __shfl_xor_sync(0xffffffffu, r1, o);
            r2 += __shfl_xor_sync(0xffffffffu, r2, o);
        }
        if (tlane == 0 && n < N_VOX) {
            out[3 * n + 0] = r0;
            out[3 * n + 1] = r1;
            out[3 * n + 2] = r2;
        }
    }
}

// ---------------------------------------------------------------------------
extern "C" void kernel_launch(void* const* d_in, const int* in_sizes, int n_in,
                              void* d_out, int out_size) {
    const float* feats = (const float*)d_in[0];
    const float* W1    = (const float*)d_in[1];
    const float* gamma = (const float*)d_in[2];
    const float* beta  = (const float*)d_in[3];
    const float* W2    = (const float*)d_in[4];
    const int*   nbr   = (const int*)  d_in[5];
    float*       out   = (float*)d_out;

    const int nblk = (N_VOX + PBLK - 1) / PBLK;

    zero_stats_kernel<<<1, 128>>>();                    // 0
    dummy_kernel<<<1, 32>>>();                          // 1
    dummy_kernel<<<1, 32>>>();                          // 2
    conv1_kernel<<<nblk, 256>>>(feats, W1, nbr);        // 3 <- ncu
    finalize_kernel<<<1, 64>>>(gamma, beta);            // 4
    conv2_kernel<<<nblk, 256>>>(W2, nbr, out);          // 5
}